// round 13
// baseline (speedup 1.0000x reference)
#include <cuda_runtime.h>
#include <stdint.h>

#define B_ 16
#define P_ 25
#define S_ 1024
#define D_ 128
#define H_ 8
#define DH_ 16
#define DFF_ 512
#define BP_ (B_*P_)
#define SIGMA_ 0.1f
#define OMEGA_ 0.5f

// output layout (flat f32 concat of the reference tuple)
#define OFF_R    0
#define OFF_Z    51200
#define OFF_PRED 102400
#define OFF_W    102800
#define OFF_K    103200
#define OFF_V    52532000
#define OFF_I    104960800

// scratch (allocation-free: __device__ globals)
__device__ __align__(16) float g_knew[BP_*D_];
__device__ __align__(16) float g_vnew[BP_*D_];
__device__ float g_pred[BP_];
__device__ int   g_idx[BP_];
__device__ int   g_cnt[B_];            // zero-init; self-resetting ticket

__device__ __forceinline__ uint32_t rotl32(uint32_t x, int d) {
    return (x << d) | (x >> (32 - d));
}

// Threefry-2x32 with key (0, 42)  [jax.random.key(42)]
__device__ __forceinline__ void threefry_0_42(uint32_t x0, uint32_t x1,
                                              uint32_t& o0, uint32_t& o1) {
    const uint32_t k0 = 0u, k1 = 42u;
    const uint32_t k2 = k0 ^ k1 ^ 0x1BD11BDAu;
    uint32_t v0 = x0 + k0, v1 = x1 + k1;
#define TF_R(r) { v0 += v1; v1 = rotl32(v1, r); v1 ^= v0; }
    TF_R(13) TF_R(15) TF_R(26) TF_R(6)
    v0 += k1; v1 += k2 + 1u;
    TF_R(17) TF_R(29) TF_R(16) TF_R(24)
    v0 += k2; v1 += k0 + 2u;
    TF_R(13) TF_R(15) TF_R(26) TF_R(6)
    v0 += k0; v1 += k1 + 3u;
    TF_R(17) TF_R(29) TF_R(16) TF_R(24)
    v0 += k1; v1 += k2 + 4u;
    TF_R(13) TF_R(15) TF_R(26) TF_R(6)
    v0 += k2; v1 += k0 + 5u;
#undef TF_R
    o0 = v0; o1 = v1;
}

// ---------------------------------------------------------------------------
// Kernel 1: fused forward + in-kernel resample. 400 blocks x 512 threads.
// Attention: single K+V streaming pass, no-max exp (scores provably small),
// __expf in the hot loop. The last block to finish a batch (per-batch atomic
// ticket) runs that batch's weight+categorical resample with the EXACT
// (precise expf/logf) math so g_idx is bit-stable.
// ---------------------------------------------------------------------------
__global__ void __launch_bounds__(512) fwd_kernel(
    const float* __restrict__ x, const float* __restrict__ K,
    const float* __restrict__ V,
    const float* __restrict__ Wq, const float* __restrict__ Wk,
    const float* __restrict__ Wv, const float* __restrict__ Wo,
    const float* __restrict__ W1, const float* __restrict__ b1,
    const float* __restrict__ W2, const float* __restrict__ b2,
    const float* __restrict__ Wout, const float* __restrict__ bout,
    const float* __restrict__ eps_k, const float* __restrict__ eps_v,
    const float* __restrict__ eps_z, const float* __restrict__ y,
    const int* __restrict__ tp, float* __restrict__ out)
{
    __shared__ float sx[D_], sq[D_], sk[D_], sv[D_];
    __shared__ float swsum[16][H_];
    __shared__ __align__(16) float sacc[16][D_];
    __shared__ float sred[4][D_];
    __shared__ float sctx[D_], sz[D_], sh1[DFF_], sr[D_];
    __shared__ float slw[P_];
    __shared__ int   sIsLast;

    const int bp   = blockIdx.x;
    const int tid  = threadIdx.x;
    const int dim  = tid & 127;
    const int grp  = tid >> 7;           // 0..3
    const int warp = tid >> 5;           // 0..15
    const int lane = tid & 31;
    const int t    = tp ? tp[0] : 512;
    const int bb   = bp / P_;            // batch index

    if (tid < D_) sx[tid] = x[bp*D_ + tid];
    __syncthreads();

    // q, k, v projections: groups 0/1/2 each handle one matrix
    if (grp < 3) {
        const float* W = (grp == 0) ? Wq : (grp == 1) ? Wk : Wv;
        float a = 0.f;
        #pragma unroll 8
        for (int d = 0; d < D_; ++d) a += sx[d] * W[d*D_ + dim];
        if (grp == 0) {
            sq[dim] = a;
        } else if (grp == 1) {
            a += SIGMA_ * eps_k[bp*D_ + dim];
            sk[dim] = a; g_knew[bp*D_ + dim] = a;
        } else {
            a += SIGMA_ * eps_v[bp*D_ + dim];
            sv[dim] = a; g_vnew[bp*D_ + dim] = a;
        }
    }
    __syncthreads();

    // attention streaming pass: 2 rows/iter per warp (4 LDG.128 in flight)
    {
        const float4* Kb = reinterpret_cast<const float4*>(K + (size_t)bp * S_ * D_);
        const float4* Vb = reinterpret_cast<const float4*>(V + (size_t)bp * S_ * D_);
        const float4  qf = reinterpret_cast<const float4*>(sq)[lane];
        const int     h  = lane >> 2;

        float sum = 0.f;
        float a0 = 0.f, a1 = 0.f, a2 = 0.f, a3 = 0.f;

        int s = warp;
        for (; s + 16 < t; s += 32) {
            float4 k0 = Kb[(size_t)s * 32 + lane];
            float4 k1 = Kb[(size_t)(s + 16) * 32 + lane];
            float4 v0 = Vb[(size_t)s * 32 + lane];
            float4 v1 = Vb[(size_t)(s + 16) * 32 + lane];
            float d0 = qf.x*k0.x + qf.y*k0.y + qf.z*k0.z + qf.w*k0.w;
            float d1 = qf.x*k1.x + qf.y*k1.y + qf.z*k1.z + qf.w*k1.w;
            d0 += __shfl_xor_sync(0xffffffffu, d0, 1);
            d1 += __shfl_xor_sync(0xffffffffu, d1, 1);
            d0 += __shfl_xor_sync(0xffffffffu, d0, 2);
            d1 += __shfl_xor_sync(0xffffffffu, d1, 2);
            float e0 = __expf(d0 * 0.25f);
            float e1 = __expf(d1 * 0.25f);
            sum += e0 + e1;
            a0 += e0*v0.x + e1*v1.x;
            a1 += e0*v0.y + e1*v1.y;
            a2 += e0*v0.z + e1*v1.z;
            a3 += e0*v0.w + e1*v1.w;
        }
        if (s < t) {
            float4 k0 = Kb[(size_t)s * 32 + lane];
            float4 v0 = Vb[(size_t)s * 32 + lane];
            float d0 = qf.x*k0.x + qf.y*k0.y + qf.z*k0.z + qf.w*k0.w;
            d0 += __shfl_xor_sync(0xffffffffu, d0, 1);
            d0 += __shfl_xor_sync(0xffffffffu, d0, 2);
            float e0 = __expf(d0 * 0.25f);
            sum += e0;
            a0 += e0*v0.x; a1 += e0*v0.y; a2 += e0*v0.z; a3 += e0*v0.w;
        }
        // s == t row comes from the freshly computed k/v in smem
        if (warp == (t & 15)) {
            float4 kv = reinterpret_cast<const float4*>(sk)[lane];
            float4 vv = reinterpret_cast<const float4*>(sv)[lane];
            float a = qf.x*kv.x + qf.y*kv.y + qf.z*kv.z + qf.w*kv.w;
            a += __shfl_xor_sync(0xffffffffu, a, 1);
            a += __shfl_xor_sync(0xffffffffu, a, 2);
            float e = __expf(a * 0.25f);
            sum += e;
            a0 += e*vv.x; a1 += e*vv.y; a2 += e*vv.z; a3 += e*vv.w;
        }
        reinterpret_cast<float4*>(sacc[warp])[lane] = make_float4(a0, a1, a2, a3);
        if ((lane & 3) == 0) swsum[warp][h] = sum;
    }
    __syncthreads();

    // combine 16 warp-partials -> ctx (plain sums; exact softmax normalize)
    if (tid < D_) {
        const int h = dim >> 4;
        float den = 0.f, num = 0.f;
        #pragma unroll
        for (int w = 0; w < 16; ++w) {
            den += swsum[w][h];
            num += sacc[w][dim];
        }
        sctx[dim] = num / den;
    }
    __syncthreads();

    // z = ctx @ Wo + sigma*eps_z   (4-way split over the 128-dim contraction)
    {
        float a = 0.f;
        #pragma unroll
        for (int d = grp*32; d < grp*32 + 32; ++d) a += sctx[d] * Wo[d*D_ + dim];
        sred[grp][dim] = a;
    }
    __syncthreads();
    if (tid < D_) {
        float a = sred[0][tid] + sred[1][tid] + sred[2][tid] + sred[3][tid]
                + SIGMA_ * eps_z[bp*D_ + tid];
        sz[tid] = a;
        out[OFF_Z + bp*D_ + tid] = a;
    }
    __syncthreads();

    // h1 = relu(z @ W1 + b1): one output per thread (128 MACs)
    {
        float a = b1[tid];
        #pragma unroll 8
        for (int d = 0; d < D_; ++d) a += sz[d] * W1[d*DFF_ + tid];
        sh1[tid] = fmaxf(a, 0.f);
    }
    __syncthreads();

    // r = h1 @ W2 + b2: 4-way split over the 512-dim contraction
    {
        float a = 0.f;
        #pragma unroll 8
        for (int f = grp*128; f < grp*128 + 128; ++f) a += sh1[f] * W2[f*D_ + dim];
        sred[grp][dim] = a;
    }
    __syncthreads();
    if (tid < D_) {
        float a = b2[tid] + sred[0][tid] + sred[1][tid] + sred[2][tid] + sred[3][tid];
        sr[tid] = a;
        out[OFF_R + bp*D_ + tid] = a;
    }
    __syncthreads();

    // pred = r @ Wout + bout  (F == 1): warp 0 reduce
    if (tid < 32) {
        float a = 0.f;
        #pragma unroll
        for (int d = tid; d < D_; d += 32) a += sr[d] * Wout[d];
        #pragma unroll
        for (int o = 16; o; o >>= 1) a += __shfl_xor_sync(0xffffffffu, a, o);
        if (tid == 0) {
            a += bout[0];
            g_pred[bp] = a;
            out[OFF_PRED + bp] = a;
        }
    }

    // -----------------------------------------------------------------------
    // Per-batch ticket: the 25th finisher runs this batch's resample.
    // -----------------------------------------------------------------------
    if (tid == 0) {
        __threadfence();
        int c = atomicAdd(&g_cnt[bb], 1);
        sIsLast = (c == P_ - 1);
    }
    __syncthreads();
    if (!sIsLast) return;

    // weights (precise math, bit-identical to the old resample_kernel)
    if (warp == 0) {
        float logw = 3.4e38f;
        if (lane < P_) {
            float mu = y[bb*4] - g_pred[bb*P_ + lane];   // y[b,0,0]
            logw = -0.5f * OMEGA_ * mu * mu;
        }
        float mn = logw;
        #pragma unroll
        for (int o = 16; o; o >>= 1) mn = fminf(mn, __shfl_xor_sync(0xffffffffu, mn, o));
        float w = (lane < P_) ? expf(logw - mn) : 0.f;
        float sum = w;
        #pragma unroll
        for (int o = 16; o; o >>= 1) sum += __shfl_xor_sync(0xffffffffu, sum, o);
        float wn = w / sum;
        if (lane < P_) {
            out[OFF_W + bb*P_ + lane] = wn;
            slw[lane] = logf(wn + 1e-10f);
        }
    }
    __syncthreads();

    const float tinyf = 1.1754943508222875e-38f;
    for (int p = warp; p < P_; p += 16) {
        float g = -3.4e38f;
        if (lane < P_) {
            uint32_t i = (uint32_t)((bb*P_ + p)*P_ + lane);
            uint32_t o0, o1;
            threefry_0_42(0u, i, o0, o1);
            uint32_t bits = o0 ^ o1;
            float u = __uint_as_float((bits >> 9) | 0x3f800000u) - 1.0f;
            u = u + tinyf;
            u = fmaxf(tinyf, u);
            g = -logf(-logf(u)) + slw[lane];
        }
        int idx = lane;
        #pragma unroll
        for (int o = 16; o; o >>= 1) {
            float og = __shfl_xor_sync(0xffffffffu, g, o);
            int   oi = __shfl_xor_sync(0xffffffffu, idx, o);
            if (og > g || (og == g && oi < idx)) { g = og; idx = oi; }
        }
        if (lane == 0) g_idx[bb*P_ + p] = idx;
    }
    __syncthreads();
    if (tid == 0) g_cnt[bb] = 0;         // self-reset for the next replay
}

// ---------------------------------------------------------------------------
// Kernel 2: K_res / V_res gather copy + fused I_new gather.
// 4 rows per warp, batched loads (MLP 8). (b,s,p)-major for L2 reuse.
// ---------------------------------------------------------------------------
__global__ void __launch_bounds__(256) copy_kv_kernel(
    const float* __restrict__ K, const float* __restrict__ V,
    const int* __restrict__ I,
    const int* __restrict__ tp, float* __restrict__ out)
{
    const int t = tp ? tp[0] : 512;
    const int warp = threadIdx.x >> 5, lane = threadIdx.x & 31;
    const int q0 = (blockIdx.x * 8 + warp) * 4;

    const float4* kp[4];
    const float4* vp[4];
    size_t dst[4];
    int bj[4], pj[4], sj[4], srcj[4];
    #pragma unroll
    for (int j = 0; j < 4; ++j) {
        int q   = q0 + j;
        int b   = q / (S_ * P_);
        int rem = q - b * (S_ * P_);
        int s   = rem / P_;
        int p   = rem - s * P_;
        int src = g_idx[b*P_ + p];
        bj[j] = b; pj[j] = p; sj[j] = s; srcj[j] = src;
        size_t srcrow = ((size_t)(b*P_ + src) * S_ + s) * 32;
        if (s == t) {
            kp[j] = reinterpret_cast<const float4*>(g_knew + (b*P_ + src)*D_);
            vp[j] = reinterpret_cast<const float4*>(g_vnew + (b*P_ + src)*D_);
        } else {
            kp[j] = reinterpret_cast<const float4*>(K) + srcrow;
            vp[j] = reinterpret_cast<const float4*>(V) + srcrow;
        }
        dst[j] = ((size_t)(b*P_ + p) * S_ + s) * 32;
    }

    float4 kr[4], vr[4];
    #pragma unroll
    for (int j = 0; j < 4; ++j) kr[j] = kp[j][lane];
    #pragma unroll
    for (int j = 0; j < 4; ++j) vr[j] = vp[j][lane];

    float4* ok = reinterpret_cast<float4*>(out + OFF_K);
    float4* ov = reinterpret_cast<float4*>(out + OFF_V);
    #pragma unroll
    for (int j = 0; j < 4; ++j) ok[dst[j] + lane] = kr[j];
    #pragma unroll
    for (int j = 0; j < 4; ++j) ov[dst[j] + lane] = vr[j];

    // fused I_new: lanes 0-3 handle one row each
    if (lane < 4) {
        int j = lane;
        int val = (sj[j] == t) ? srcj[j]
                : I[((size_t)(bj[j]*P_ + srcj[j])) * S_ + sj[j]];
        out[OFF_I + ((size_t)(bj[j]*P_ + pj[j]) * S_ + sj[j])] = (float)val;
    }
}

extern "C" void kernel_launch(void* const* d_in, const int* in_sizes, int n_in,
                              void* d_out, int out_size)
{
    const float* x     = (const float*)d_in[0];
    const float* y     = (const float*)d_in[1];
    const float* K     = (const float*)d_in[2];
    const float* V     = (const float*)d_in[3];
    /* w = d_in[4] unused */
    const int*   I     = (const int*)  d_in[5];
    const float* Wq    = (const float*)d_in[6];
    const float* Wk    = (const float*)d_in[7];
    const float* Wv    = (const float*)d_in[8];
    const float* Wo    = (const float*)d_in[9];
    const float* W1    = (const float*)d_in[10];
    const float* b1    = (const float*)d_in[11];
    const float* W2    = (const float*)d_in[12];
    const float* b2    = (const float*)d_in[13];
    const float* Wout  = (const float*)d_in[14];
    const float* bout  = (const float*)d_in[15];
    const float* eps_k = (const float*)d_in[16];
    const float* eps_v = (const float*)d_in[17];
    const float* eps_z = (const float*)d_in[18];
    const int*   tp    = (n_in > 19) ? (const int*)d_in[19] : nullptr;
    float* out = (float*)d_out;

    fwd_kernel<<<BP_, 512>>>(x, K, V, Wq, Wk, Wv, Wo, W1, b1, W2, b2,
                             Wout, bout, eps_k, eps_v, eps_z, y, tp, out);
    copy_kv_kernel<<<BP_ * S_ / 32, 256>>>(K, V, I, tp, out);
}

// round 15
// speedup vs baseline: 1.0478x; 1.0478x over previous
#include <cuda_runtime.h>
#include <stdint.h>

#define B_ 16
#define P_ 25
#define S_ 1024
#define D_ 128
#define H_ 8
#define DH_ 16
#define DFF_ 512
#define BP_ (B_*P_)
#define SIGMA_ 0.1f
#define OMEGA_ 0.5f

// output layout (flat f32 concat of the reference tuple)
#define OFF_R    0
#define OFF_Z    51200
#define OFF_PRED 102400
#define OFF_W    102800
#define OFF_K    103200
#define OFF_V    52532000
#define OFF_I    104960800

#define NKV_BLOCKS (BP_*S_/32)          // 12800
#define NI_BLOCKS  (BP_*S_/4/256)       // 400

// scratch (allocation-free: __device__ globals)
__device__ __align__(16) float g_knew[BP_*D_];
__device__ __align__(16) float g_vnew[BP_*D_];
__device__ float g_pred[BP_];
__device__ int   g_idx[BP_];
__device__ int   g_cnt[B_];             // zero-init; self-resetting ticket

__device__ __forceinline__ uint32_t rotl32(uint32_t x, int d) {
    return (x << d) | (x >> (32 - d));
}

// Threefry-2x32 with key (0, 42)  [jax.random.key(42)]
__device__ __forceinline__ void threefry_0_42(uint32_t x0, uint32_t x1,
                                              uint32_t& o0, uint32_t& o1) {
    const uint32_t k0 = 0u, k1 = 42u;
    const uint32_t k2 = k0 ^ k1 ^ 0x1BD11BDAu;
    uint32_t v0 = x0 + k0, v1 = x1 + k1;
#define TF_R(r) { v0 += v1; v1 = rotl32(v1, r); v1 ^= v0; }
    TF_R(13) TF_R(15) TF_R(26) TF_R(6)
    v0 += k1; v1 += k2 + 1u;
    TF_R(17) TF_R(29) TF_R(16) TF_R(24)
    v0 += k2; v1 += k0 + 2u;
    TF_R(13) TF_R(15) TF_R(26) TF_R(6)
    v0 += k0; v1 += k1 + 3u;
    TF_R(17) TF_R(29) TF_R(16) TF_R(24)
    v0 += k1; v1 += k2 + 4u;
    TF_R(13) TF_R(15) TF_R(26) TF_R(6)
    v0 += k2; v1 += k0 + 5u;
#undef TF_R
    o0 = v0; o1 = v1;
}

// ---------------------------------------------------------------------------
// Kernel 1: fused forward + in-kernel resample. 400 blocks x 512 threads.
// ---------------------------------------------------------------------------
__global__ void __launch_bounds__(512) fwd_kernel(
    const float* __restrict__ x, const float* __restrict__ K,
    const float* __restrict__ V,
    const float* __restrict__ Wq, const float* __restrict__ Wk,
    const float* __restrict__ Wv, const float* __restrict__ Wo,
    const float* __restrict__ W1, const float* __restrict__ b1,
    const float* __restrict__ W2, const float* __restrict__ b2,
    const float* __restrict__ Wout, const float* __restrict__ bout,
    const float* __restrict__ eps_k, const float* __restrict__ eps_v,
    const float* __restrict__ eps_z, const float* __restrict__ y,
    const int* __restrict__ tp, float* __restrict__ out)
{
    __shared__ float sx[D_], sq[D_], sk[D_], sv[D_];
    __shared__ float swsum[16][H_];
    __shared__ __align__(16) float sacc[16][D_];
    __shared__ float sred[4][D_];
    __shared__ float sctx[D_], sz[D_], sh1[DFF_], sr[D_];
    __shared__ float slw[P_];
    __shared__ int   sIsLast;

    const int bp   = blockIdx.x;
    const int tid  = threadIdx.x;
    const int dim  = tid & 127;
    const int grp  = tid >> 7;           // 0..3
    const int warp = tid >> 5;           // 0..15
    const int lane = tid & 31;
    const int t    = tp ? tp[0] : 512;
    const int bb   = bp / P_;            // batch index

    if (tid < D_) sx[tid] = x[bp*D_ + tid];
    __syncthreads();

    // q, k, v projections: groups 0/1/2 each handle one matrix
    if (grp < 3) {
        const float* W = (grp == 0) ? Wq : (grp == 1) ? Wk : Wv;
        float a = 0.f;
        #pragma unroll 8
        for (int d = 0; d < D_; ++d) a += sx[d] * W[d*D_ + dim];
        if (grp == 0) {
            sq[dim] = a;
        } else if (grp == 1) {
            a += SIGMA_ * eps_k[bp*D_ + dim];
            sk[dim] = a; g_knew[bp*D_ + dim] = a;
        } else {
            a += SIGMA_ * eps_v[bp*D_ + dim];
            sv[dim] = a; g_vnew[bp*D_ + dim] = a;
        }
    }
    __syncthreads();

    // attention streaming pass: 2 rows/iter per warp (4 LDG.128 in flight)
    {
        const float4* Kb = reinterpret_cast<const float4*>(K + (size_t)bp * S_ * D_);
        const float4* Vb = reinterpret_cast<const float4*>(V + (size_t)bp * S_ * D_);
        const float4  qf = reinterpret_cast<const float4*>(sq)[lane];
        const int     h  = lane >> 2;

        float sum = 0.f;
        float a0 = 0.f, a1 = 0.f, a2 = 0.f, a3 = 0.f;

        int s = warp;
        for (; s + 16 < t; s += 32) {
            float4 k0 = Kb[(size_t)s * 32 + lane];
            float4 k1 = Kb[(size_t)(s + 16) * 32 + lane];
            float4 v0 = Vb[(size_t)s * 32 + lane];
            float4 v1 = Vb[(size_t)(s + 16) * 32 + lane];
            float d0 = qf.x*k0.x + qf.y*k0.y + qf.z*k0.z + qf.w*k0.w;
            float d1 = qf.x*k1.x + qf.y*k1.y + qf.z*k1.z + qf.w*k1.w;
            d0 += __shfl_xor_sync(0xffffffffu, d0, 1);
            d1 += __shfl_xor_sync(0xffffffffu, d1, 1);
            d0 += __shfl_xor_sync(0xffffffffu, d0, 2);
            d1 += __shfl_xor_sync(0xffffffffu, d1, 2);
            float e0 = __expf(d0 * 0.25f);
            float e1 = __expf(d1 * 0.25f);
            sum += e0 + e1;
            a0 += e0*v0.x + e1*v1.x;
            a1 += e0*v0.y + e1*v1.y;
            a2 += e0*v0.z + e1*v1.z;
            a3 += e0*v0.w + e1*v1.w;
        }
        if (s < t) {
            float4 k0 = Kb[(size_t)s * 32 + lane];
            float4 v0 = Vb[(size_t)s * 32 + lane];
            float d0 = qf.x*k0.x + qf.y*k0.y + qf.z*k0.z + qf.w*k0.w;
            d0 += __shfl_xor_sync(0xffffffffu, d0, 1);
            d0 += __shfl_xor_sync(0xffffffffu, d0, 2);
            float e0 = __expf(d0 * 0.25f);
            sum += e0;
            a0 += e0*v0.x; a1 += e0*v0.y; a2 += e0*v0.z; a3 += e0*v0.w;
        }
        // s == t row comes from the freshly computed k/v in smem
        if (warp == (t & 15)) {
            float4 kv = reinterpret_cast<const float4*>(sk)[lane];
            float4 vv = reinterpret_cast<const float4*>(sv)[lane];
            float a = qf.x*kv.x + qf.y*kv.y + qf.z*kv.z + qf.w*kv.w;
            a += __shfl_xor_sync(0xffffffffu, a, 1);
            a += __shfl_xor_sync(0xffffffffu, a, 2);
            float e = __expf(a * 0.25f);
            sum += e;
            a0 += e*vv.x; a1 += e*vv.y; a2 += e*vv.z; a3 += e*vv.w;
        }
        reinterpret_cast<float4*>(sacc[warp])[lane] = make_float4(a0, a1, a2, a3);
        if ((lane & 3) == 0) swsum[warp][h] = sum;
    }
    __syncthreads();

    // combine 16 warp-partials -> ctx (plain sums; exact softmax normalize)
    if (tid < D_) {
        const int h = dim >> 4;
        float den = 0.f, num = 0.f;
        #pragma unroll
        for (int w = 0; w < 16; ++w) {
            den += swsum[w][h];
            num += sacc[w][dim];
        }
        sctx[dim] = num / den;
    }
    __syncthreads();

    // z = ctx @ Wo + sigma*eps_z   (4-way split over the 128-dim contraction)
    {
        float a = 0.f;
        #pragma unroll
        for (int d = grp*32; d < grp*32 + 32; ++d) a += sctx[d] * Wo[d*D_ + dim];
        sred[grp][dim] = a;
    }
    __syncthreads();
    if (tid < D_) {
        float a = sred[0][tid] + sred[1][tid] + sred[2][tid] + sred[3][tid]
                + SIGMA_ * eps_z[bp*D_ + tid];
        sz[tid] = a;
        out[OFF_Z + bp*D_ + tid] = a;
    }
    __syncthreads();

    // h1 = relu(z @ W1 + b1): one output per thread (128 MACs)
    {
        float a = b1[tid];
        #pragma unroll 8
        for (int d = 0; d < D_; ++d) a += sz[d] * W1[d*DFF_ + tid];
        sh1[tid] = fmaxf(a, 0.f);
    }
    __syncthreads();

    // r = h1 @ W2 + b2: 4-way split over the 512-dim contraction
    {
        float a = 0.f;
        #pragma unroll 8
        for (int f = grp*128; f < grp*128 + 128; ++f) a += sh1[f] * W2[f*D_ + dim];
        sred[grp][dim] = a;
    }
    __syncthreads();
    if (tid < D_) {
        float a = b2[tid] + sred[0][tid] + sred[1][tid] + sred[2][tid] + sred[3][tid];
        sr[tid] = a;
        out[OFF_R + bp*D_ + tid] = a;
    }
    __syncthreads();

    // pred = r @ Wout + bout  (F == 1): warp 0 reduce
    if (tid < 32) {
        float a = 0.f;
        #pragma unroll
        for (int d = tid; d < D_; d += 32) a += sr[d] * Wout[d];
        #pragma unroll
        for (int o = 16; o; o >>= 1) a += __shfl_xor_sync(0xffffffffu, a, o);
        if (tid == 0) {
            a += bout[0];
            g_pred[bp] = a;
            out[OFF_PRED + bp] = a;
        }
    }

    // -----------------------------------------------------------------------
    // Per-batch ticket: the 25th finisher runs this batch's resample.
    // -----------------------------------------------------------------------
    if (tid == 0) {
        __threadfence();
        int c = atomicAdd(&g_cnt[bb], 1);
        sIsLast = (c == P_ - 1);
    }
    __syncthreads();
    if (!sIsLast) return;

    // weights (precise math, bit-identical to the standalone resample kernel)
    if (warp == 0) {
        float logw = 3.4e38f;
        if (lane < P_) {
            float mu = y[bb*4] - g_pred[bb*P_ + lane];   // y[b,0,0]
            logw = -0.5f * OMEGA_ * mu * mu;
        }
        float mn = logw;
        #pragma unroll
        for (int o = 16; o; o >>= 1) mn = fminf(mn, __shfl_xor_sync(0xffffffffu, mn, o));
        float w = (lane < P_) ? expf(logw - mn) : 0.f;
        float sum = w;
        #pragma unroll
        for (int o = 16; o; o >>= 1) sum += __shfl_xor_sync(0xffffffffu, sum, o);
        float wn = w / sum;
        if (lane < P_) {
            out[OFF_W + bb*P_ + lane] = wn;
            slw[lane] = logf(wn + 1e-10f);
        }
    }
    __syncthreads();

    const float tinyf = 1.1754943508222875e-38f;
    for (int p = warp; p < P_; p += 16) {
        float g = -3.4e38f;
        if (lane < P_) {
            uint32_t i = (uint32_t)((bb*P_ + p)*P_ + lane);
            uint32_t o0, o1;
            threefry_0_42(0u, i, o0, o1);
            uint32_t bits = o0 ^ o1;
            float u = __uint_as_float((bits >> 9) | 0x3f800000u) - 1.0f;
            u = u + tinyf;
            u = fmaxf(tinyf, u);
            g = -logf(-logf(u)) + slw[lane];
        }
        int idx = lane;
        #pragma unroll
        for (int o = 16; o; o >>= 1) {
            float og = __shfl_xor_sync(0xffffffffu, g, o);
            int   oi = __shfl_xor_sync(0xffffffffu, idx, o);
            if (og > g || (og == g && oi < idx)) { g = og; idx = oi; }
        }
        if (lane == 0) g_idx[bb*P_ + p] = idx;
    }
    __syncthreads();
    if (tid == 0) g_cnt[bb] = 0;         // self-reset for the next replay
}

// ---------------------------------------------------------------------------
// Kernel 2: two-branch copy.
//   blocks [0, NKV_BLOCKS): K_res/V_res gather, 4 rows/warp, batched loads
//     (MLP 8), NO index arrays kept live -> low regs, high occupancy.
//   blocks [NKV_BLOCKS, +NI_BLOCKS): I_new gather, int4-vectorized.
// ---------------------------------------------------------------------------
__global__ void __launch_bounds__(256) copy_kv_kernel(
    const float* __restrict__ K, const float* __restrict__ V,
    const int* __restrict__ I,
    const int* __restrict__ tp, float* __restrict__ out)
{
    const int t = tp ? tp[0] : 512;

    if (blockIdx.x < NKV_BLOCKS) {
        const int warp = threadIdx.x >> 5, lane = threadIdx.x & 31;
        const int q0 = (blockIdx.x * 8 + warp) * 4;

        const float4* kp[4];
        const float4* vp[4];
        size_t dst[4];
        #pragma unroll
        for (int j = 0; j < 4; ++j) {
            int q   = q0 + j;
            int b   = q / (S_ * P_);
            int rem = q - b * (S_ * P_);
            int s   = rem / P_;
            int p   = rem - s * P_;
            int src = g_idx[b*P_ + p];
            size_t srcrow = ((size_t)(b*P_ + src) * S_ + s) * 32;
            if (s == t) {
                kp[j] = reinterpret_cast<const float4*>(g_knew + (b*P_ + src)*D_);
                vp[j] = reinterpret_cast<const float4*>(g_vnew + (b*P_ + src)*D_);
            } else {
                kp[j] = reinterpret_cast<const float4*>(K) + srcrow;
                vp[j] = reinterpret_cast<const float4*>(V) + srcrow;
            }
            dst[j] = ((size_t)(b*P_ + p) * S_ + s) * 32;
        }

        float4 kr[4], vr[4];
        #pragma unroll
        for (int j = 0; j < 4; ++j) kr[j] = kp[j][lane];
        #pragma unroll
        for (int j = 0; j < 4; ++j) vr[j] = vp[j][lane];

        float4* ok = reinterpret_cast<float4*>(out + OFF_K);
        float4* ov = reinterpret_cast<float4*>(out + OFF_V);
        #pragma unroll
        for (int j = 0; j < 4; ++j) ok[dst[j] + lane] = kr[j];
        #pragma unroll
        for (int j = 0; j < 4; ++j) ov[dst[j] + lane] = vr[j];
    } else {
        // I_new gather: one int4 group per thread
        const int gid = (blockIdx.x - NKV_BLOCKS) * 256 + threadIdx.x;
        const int base = gid * 4;
        const int b    = base / (P_ * S_);
        const int rem  = base - b * (P_ * S_);
        const int p    = rem >> 10;
        const int s0   = rem & (S_ - 1);
        const int src  = g_idx[b*P_ + p];

        int4 v = *reinterpret_cast<const int4*>(
            I + ((size_t)(b*P_ + src) * S_ + s0));
        int vals[4] = {v.x, v.y, v.z, v.w};
        #pragma unroll
        for (int j = 0; j < 4; ++j)
            if (s0 + j == t) vals[j] = src;

        float4 fv = make_float4((float)vals[0], (float)vals[1],
                                (float)vals[2], (float)vals[3]);
        *reinterpret_cast<float4*>(out + OFF_I + base) = fv;
    }
}

extern "C" void kernel_launch(void* const* d_in, const int* in_sizes, int n_in,
                              void* d_out, int out_size)
{
    const float* x     = (const float*)d_in[0];
    const float* y     = (const float*)d_in[1];
    const float* K     = (const float*)d_in[2];
    const float* V     = (const float*)d_in[3];
    /* w = d_in[4] unused */
    const int*   I     = (const int*)  d_in[5];
    const float* Wq    = (const float*)d_in[6];
    const float* Wk    = (const float*)d_in[7];
    const float* Wv    = (const float*)d_in[8];
    const float* Wo    = (const float*)d_in[9];
    const float* W1    = (const float*)d_in[10];
    const float* b1    = (const float*)d_in[11];
    const float* W2    = (const float*)d_in[12];
    const float* b2    = (const float*)d_in[13];
    const float* Wout  = (const float*)d_in[14];
    const float* bout  = (const float*)d_in[15];
    const float* eps_k = (const float*)d_in[16];
    const float* eps_v = (const float*)d_in[17];
    const float* eps_z = (const float*)d_in[18];
    const int*   tp    = (n_in > 19) ? (const int*)d_in[19] : nullptr;
    float* out = (float*)d_out;

    fwd_kernel<<<BP_, 512>>>(x, K, V, Wq, Wk, Wv, Wo, W1, b1, W2, b2,
                             Wout, bout, eps_k, eps_v, eps_z, y, tp, out);
    copy_kv_kernel<<<NKV_BLOCKS + NI_BLOCKS, 256>>>(K, V, I, tp, out);
}